// round 12
// baseline (speedup 1.0000x reference)
#include <cuda_runtime.h>

// RollingBufferCache: B=4, H=8, S=512, D=128, BUF=4096.
// Output = [k_window ; v_window], each [B,H,W,D] with W = min(cur, BUF).
// W == BUF here, so every physical slot appears exactly once in the window:
// scatter+gather collapses to a per-row source selection:
//   w >= W-S  -> new chunk row (w - (W-S))
//   otherwise -> cache row (cur - W + w) & (BUF-1)
//
// FINAL (R2 structure; reproduced R7-R11): fastest of 8 measured variants.
// Kernel 36.1-37.3us = 268MB at ~7.4 TB/s combined R+W (~93% of HBM3e spec)
// — the memory floor for a fully mixed single-use R/W stream. Bench dur for
// this identical binary spans 43.5-45.4us (harness replay + clock-state
// noise); the kernel-time counter is the trusted metric.
//
// Structure: one warp per 512B row, 4 rows per warp with front-batched loads
// (MLP=4/thread), streaming evict-first (.cs) both directions, 32 regs ->
// ~81% occupancy, 8192-CTA launch.
// Measured neutral-or-negative alternatives: 256-bit v8 accesses (+16 regs,
// occ 51%, -2.3us kernel), persistent grid (div/mod ALU tax, -2.2us), 4-tile
// CTA reuse (+8 regs, -1.2us), CTA-level load/store phase barrier (neutral).
// Traffic is provably minimal (every output byte sourced from a unique input
// byte, written once); latency 8x over-covered -> no remaining levers.

#define ROLL_D4   32    // D/4 float4 per row (D=128)
#define ROLL_BH   32    // B*H
#define ROLL_BUF  4096
#define ROLL_S    512

__global__ void __launch_bounds__(256)
RollingBufferCache_kernel(const float4* __restrict__ k,
                          const float4* __restrict__ v,
                          const float4* __restrict__ kc,
                          const float4* __restrict__ vc,
                          const int*    __restrict__ cur_p,
                          float4*       __restrict__ out,
                          int W)
{
    const int cur  = __ldg(cur_p);        // device scalar (graph-capturable)
    const int sel  = blockIdx.z;          // 0 = k path, 1 = v path
    const int bh   = blockIdx.y;          // flattened (b,h)
    const int lane = threadIdx.x & 31;
    const int warp = threadIdx.x >> 5;

    const float4* src_new = sel ? v  : k;
    const float4* src_old = sel ? vc : kc;
    float4* out_base = out + ((size_t)(sel * ROLL_BH + bh) * (size_t)W) * ROLL_D4;

    const int off    = cur - W;           // logical start of window
    const int wsplit = W - ROLL_S;        // rows >= wsplit come from new chunk

    // Each block covers 32 consecutive rows of one (sel,bh); 8 warps,
    // each warp does 4 rows (512 B each), one float4 per lane.
    // W is a multiple of 32 for this grid -> no bounds checks.
    const int w0 = blockIdx.x * 32 + warp;

    // Phase 1: compute all 4 source addresses, issue all 4 loads (MLP=4).
    const float4* srow[4];
    #pragma unroll
    for (int r = 0; r < 4; ++r) {
        const int w = w0 + r * 8;
        if (w >= wsplit) {
            srow[r] = src_new + ((size_t)bh * ROLL_S + (size_t)(w - wsplit)) * ROLL_D4;
        } else {
            const int phys = (off + w) & (ROLL_BUF - 1);
            srow[r] = src_old + ((size_t)bh * ROLL_BUF + (size_t)phys) * ROLL_D4;
        }
    }

    float4 val[4];
    #pragma unroll
    for (int r = 0; r < 4; ++r)
        val[r] = __ldcs(srow[r] + lane);   // evict-first: single-use stream

    // Phase 2: store all 4 (streaming, evict-first).
    #pragma unroll
    for (int r = 0; r < 4; ++r)
        __stcs(out_base + (size_t)(w0 + r * 8) * ROLL_D4 + lane, val[r]);
}

extern "C" void kernel_launch(void* const* d_in, const int* in_sizes, int n_in,
                              void* d_out, int out_size)
{
    const float4* k  = (const float4*)d_in[0];
    const float4* v  = (const float4*)d_in[1];
    const float4* kc = (const float4*)d_in[2];
    const float4* vc = (const float4*)d_in[3];
    const int*   cur = (const int*)d_in[4];

    // out_size = 2 * BH * W * D  ->  W
    const int W = out_size / (2 * ROLL_BH * 128);

    dim3 grid((W + 31) / 32, ROLL_BH, 2);
    RollingBufferCache_kernel<<<grid, 256>>>(k, v, kc, vc, cur,
                                             (float4*)d_out, W);
}

// round 13
// speedup vs baseline: 1.0434x; 1.0434x over previous
#include <cuda_runtime.h>

// RollingBufferCache: B=4, H=8, S=512, D=128, BUF=4096.
// Output = [k_window ; v_window], each [B,H,W,D] with W = min(cur, BUF).
// W == BUF here, so every physical slot appears exactly once in the window:
// scatter+gather collapses to a per-row source selection:
//   w >= W-S  -> new chunk row (w - (W-S))
//   otherwise -> cache row (cur - W + w) & (BUF-1)
//
// FINAL (R2 structure; reproduced R7-R12, 7 runs): fastest of 8 measured
// variants. Kernel 36.1-37.5us = 268MB at 7.15-7.42 TB/s combined R+W
// (90-93% of HBM3e spec) — the memory floor for a fully mixed single-use
// R/W stream. Bench dur for this identical binary spans 43.5-45.4us;
// DRAM% co-varies with kernel time run-to-run, so the variance is chip
// clock/thermal state, not code. Kernel-time counter is the trusted metric.
//
// Structure: one warp per 512B row, 4 rows per warp with front-batched loads
// (MLP=4/thread), streaming evict-first (.cs) both directions, 32 regs ->
// ~81% occupancy, 8192-CTA launch.
// Measured neutral-or-negative alternatives: 256-bit v8 accesses (+16 regs,
// occ 51%, -2.3us kernel), persistent grid (div/mod ALU tax, -2.2us), 4-tile
// CTA reuse (+8 regs, -1.2us), CTA-level load/store phase barrier (neutral).
// Traffic is provably minimal (every output byte sourced from a unique input
// byte, written once); latency 8x over-covered -> no remaining levers.

#define ROLL_D4   32    // D/4 float4 per row (D=128)
#define ROLL_BH   32    // B*H
#define ROLL_BUF  4096
#define ROLL_S    512

__global__ void __launch_bounds__(256)
RollingBufferCache_kernel(const float4* __restrict__ k,
                          const float4* __restrict__ v,
                          const float4* __restrict__ kc,
                          const float4* __restrict__ vc,
                          const int*    __restrict__ cur_p,
                          float4*       __restrict__ out,
                          int W)
{
    const int cur  = __ldg(cur_p);        // device scalar (graph-capturable)
    const int sel  = blockIdx.z;          // 0 = k path, 1 = v path
    const int bh   = blockIdx.y;          // flattened (b,h)
    const int lane = threadIdx.x & 31;
    const int warp = threadIdx.x >> 5;

    const float4* src_new = sel ? v  : k;
    const float4* src_old = sel ? vc : kc;
    float4* out_base = out + ((size_t)(sel * ROLL_BH + bh) * (size_t)W) * ROLL_D4;

    const int off    = cur - W;           // logical start of window
    const int wsplit = W - ROLL_S;        // rows >= wsplit come from new chunk

    // Each block covers 32 consecutive rows of one (sel,bh); 8 warps,
    // each warp does 4 rows (512 B each), one float4 per lane.
    // W is a multiple of 32 for this grid -> no bounds checks.
    const int w0 = blockIdx.x * 32 + warp;

    // Phase 1: compute all 4 source addresses, issue all 4 loads (MLP=4).
    const float4* srow[4];
    #pragma unroll
    for (int r = 0; r < 4; ++r) {
        const int w = w0 + r * 8;
        if (w >= wsplit) {
            srow[r] = src_new + ((size_t)bh * ROLL_S + (size_t)(w - wsplit)) * ROLL_D4;
        } else {
            const int phys = (off + w) & (ROLL_BUF - 1);
            srow[r] = src_old + ((size_t)bh * ROLL_BUF + (size_t)phys) * ROLL_D4;
        }
    }

    float4 val[4];
    #pragma unroll
    for (int r = 0; r < 4; ++r)
        val[r] = __ldcs(srow[r] + lane);   // evict-first: single-use stream

    // Phase 2: store all 4 (streaming, evict-first).
    #pragma unroll
    for (int r = 0; r < 4; ++r)
        __stcs(out_base + (size_t)(w0 + r * 8) * ROLL_D4 + lane, val[r]);
}

extern "C" void kernel_launch(void* const* d_in, const int* in_sizes, int n_in,
                              void* d_out, int out_size)
{
    const float4* k  = (const float4*)d_in[0];
    const float4* v  = (const float4*)d_in[1];
    const float4* kc = (const float4*)d_in[2];
    const float4* vc = (const float4*)d_in[3];
    const int*   cur = (const int*)d_in[4];

    // out_size = 2 * BH * W * D  ->  W
    const int W = out_size / (2 * ROLL_BH * 128);

    dim3 grid((W + 31) / 32, ROLL_BH, 2);
    RollingBufferCache_kernel<<<grid, 256>>>(k, v, kc, vc, cur,
                                             (float4*)d_out, W);
}